// round 5
// baseline (speedup 1.0000x reference)
#include <cuda_runtime.h>
#include <cstdint>
#include <math.h>

// Problem constants
#define LL 1024
#define BB 2
#define FF 1024
#define HH 2048
#define NN 16
#define RR 64
#define KK 4
#define MROWS (LL*BB)        // 2048
#define PROJC (RR + 2*NN)    // 96

// ---------------- scratch (device globals: allocation-free) ----------------
__device__ float g_h[(size_t)MROWS * (2*HH)];   // xs(rounded) | res(raw)
__device__ float g_u[(size_t)MROWS * HH];       // rounded
__device__ float g_proj[(size_t)MROWS * PROJC]; // rounded
__device__ float g_delta[(size_t)MROWS * HH];   // raw (scan only)
__device__ float g_z[(size_t)MROWS * HH];       // rounded
// TF32-rounded copies of inputs/weights
__device__ float g_rx   [(size_t)MROWS * FF];
__device__ float g_rWin [(size_t)FF * 2 * HH];
__device__ float g_rWc  [(size_t)KK * 1024 * HH];
__device__ float g_rWssm[(size_t)HH * PROJC];
__device__ float g_rWdt [(size_t)RR * HH];
__device__ float g_rWout[(size_t)HH * FF];

#define BM 128
#define BN 128
#define BK 16
#define AS_S 20
#define BS_S 136

__device__ __forceinline__ float sigmoid_f(float x) {
    return 1.f / (1.f + __expf(-x));
}
__device__ __forceinline__ float tf32r(float f) {
    unsigned u;
    asm("cvt.rna.tf32.f32 %0, %1;" : "=r"(u) : "f"(f));
    return __uint_as_float(u);
}
__device__ __forceinline__ void mma_tf32(float* d, const unsigned* a, const unsigned* b) {
    asm volatile(
        "mma.sync.aligned.m16n8k8.row.col.f32.tf32.tf32.f32 "
        "{%0,%1,%2,%3}, {%4,%5,%6,%7}, {%8,%9}, {%0,%1,%2,%3};\n"
        : "+f"(d[0]), "+f"(d[1]), "+f"(d[2]), "+f"(d[3])
        : "r"(a[0]), "r"(a[1]), "r"(a[2]), "r"(a[3]), "r"(b[0]), "r"(b[1]));
}
__device__ __forceinline__ void cp16(float* smem_dst, const float* gsrc, bool valid) {
    unsigned int s = (unsigned int)__cvta_generic_to_shared(smem_dst);
    int sz = valid ? 16 : 0;
    asm volatile("cp.async.cg.shared.global [%0], [%1], 16, %2;\n"
                 :: "r"(s), "l"(gsrc), "r"(sz));
}
#define CP_COMMIT() asm volatile("cp.async.commit_group;\n")
#define CP_WAIT0()  asm volatile("cp.async.wait_group 0;\n")

// ---------------- TF32 pre-round (elementwise, float4) ---------------------
__global__ void round_k(const float* __restrict__ in, float* __restrict__ out, int n4)
{
    int i = blockIdx.x * blockDim.x + threadIdx.x;
    if (i < n4) {
        float4 v = reinterpret_cast<const float4*>(in)[i];
        v.x = tf32r(v.x); v.y = tf32r(v.y); v.z = tf32r(v.z); v.w = tf32r(v.w);
        reinterpret_cast<float4*>(out)[i] = v;
    }
}

// ================= TF32 tensor-core GEMM, 128x128xK, 256 thr ==============
// EPI: 0 = plain, 1 = softplus(acc+bias), no round
// RND: 0 = none, 1 = round all stores to tf32, 2 = round only cols < HH
template<int EPI, int RND>
__global__ __launch_bounds__(256, 2)
void gemm_k(const float* __restrict__ A, int lda,
            const float* __restrict__ B, int ldb,
            float* __restrict__ C, int ldc,
            int Nn, int Kk, const float* __restrict__ bias)
{
    __shared__ float As[2][BM][AS_S];
    __shared__ float Bs[2][BK][BS_S];

    const int tid  = threadIdx.x;
    const int row0 = blockIdx.y * BM;
    const int col0 = blockIdx.x * BN;
    const int warp = tid >> 5;
    const int lane = tid & 31;
    const int gid  = lane >> 2;
    const int tig  = lane & 3;
    const int wm0  = (warp & 3) * 32;
    const int wn0  = (warp >> 2) * 64;

    auto ld_tile = [&](int kt, int buf) {
#pragma unroll
        for (int i = 0; i < 2; i++) {
            int s = tid + i * 256, m = s >> 2, j = (s & 3) << 2;
            cp16(&As[buf][m][j], &A[(size_t)(row0 + m) * lda + kt + j], true);
        }
#pragma unroll
        for (int i = 0; i < 2; i++) {
            int s = tid + i * 256, kk = s >> 5, col = (s & 31) << 2;
            cp16(&Bs[buf][kk][col], &B[(size_t)(kt + kk) * ldb + col0 + col],
                 col0 + col < Nn);
        }
        CP_COMMIT();
    };

    float acc[2][8][4];
#pragma unroll
    for (int mt = 0; mt < 2; mt++)
#pragma unroll
        for (int nt = 0; nt < 8; nt++)
#pragma unroll
            for (int q = 0; q < 4; q++) acc[mt][nt][q] = 0.f;

    ld_tile(0, 0);
    CP_WAIT0();
    __syncthreads();

    const int T = Kk / BK;
    for (int t = 0; t < T; t++) {
        const int buf = t & 1;
        if (t + 1 < T) ld_tile((t + 1) * BK, buf ^ 1);

#pragma unroll
        for (int ks = 0; ks < 2; ks++) {
            const int k0 = ks * 8;
            unsigned a[2][4], b[8][2];
#pragma unroll
            for (int mt = 0; mt < 2; mt++) {
                int mr = wm0 + mt * 16;
                a[mt][0] = __float_as_uint(As[buf][mr + gid    ][k0 + tig]);
                a[mt][1] = __float_as_uint(As[buf][mr + gid + 8][k0 + tig]);
                a[mt][2] = __float_as_uint(As[buf][mr + gid    ][k0 + tig + 4]);
                a[mt][3] = __float_as_uint(As[buf][mr + gid + 8][k0 + tig + 4]);
            }
#pragma unroll
            for (int nt = 0; nt < 8; nt++) {
                int nc = wn0 + nt * 8;
                b[nt][0] = __float_as_uint(Bs[buf][k0 + tig    ][nc + gid]);
                b[nt][1] = __float_as_uint(Bs[buf][k0 + tig + 4][nc + gid]);
            }
#pragma unroll
            for (int mt = 0; mt < 2; mt++)
#pragma unroll
                for (int nt = 0; nt < 8; nt++)
                    mma_tf32(acc[mt][nt], a[mt], b[nt]);
        }

        if (t + 1 < T) {
            CP_WAIT0();
            __syncthreads();
        }
    }

#pragma unroll
    for (int mt = 0; mt < 2; mt++) {
        int r = row0 + wm0 + mt * 16 + gid;
#pragma unroll
        for (int nt = 0; nt < 8; nt++) {
            int c = col0 + wn0 + nt * 8 + tig * 2;
            if (c < Nn) {
                float v0 = acc[mt][nt][0], v1 = acc[mt][nt][1];
                float v2 = acc[mt][nt][2], v3 = acc[mt][nt][3];
                if (EPI == 1) {
                    v0 += bias[c];     v0 = (v0 > 20.f) ? v0 : log1pf(expf(v0));
                    v1 += bias[c + 1]; v1 = (v1 > 20.f) ? v1 : log1pf(expf(v1));
                    v2 += bias[c];     v2 = (v2 > 20.f) ? v2 : log1pf(expf(v2));
                    v3 += bias[c + 1]; v3 = (v3 > 20.f) ? v3 : log1pf(expf(v3));
                }
                if (RND == 1 || (RND == 2 && c < HH)) {
                    v0 = tf32r(v0); v1 = tf32r(v1); v2 = tf32r(v2); v3 = tf32r(v3);
                }
                C[(size_t)r * ldc + c]           = v0;
                C[(size_t)r * ldc + c + 1]       = v1;
                C[(size_t)(r + 8) * ldc + c]     = v2;
                C[(size_t)(r + 8) * ldc + c + 1] = v3;
            }
        }
    }
}

// ===== causal grouped conv (4 taps, 2 groups) as shifted TF32 GEMM ========
__global__ __launch_bounds__(256, 2)
void conv_silu_k(const float* __restrict__ h, const float* __restrict__ Wc,
                 const float* __restrict__ bconv, float* __restrict__ U)
{
    __shared__ float As[2][BM][AS_S];
    __shared__ float Bs[2][BK][BS_S];

    const int tid  = threadIdx.x;
    const int row0 = blockIdx.y * BM;
    const int col0 = blockIdx.x * BN;
    const int grp  = col0 >> 10;
    const int warp = tid >> 5;
    const int lane = tid & 31;
    const int gid  = lane >> 2;
    const int tig  = lane & 3;
    const int wm0  = (warp & 3) * 32;
    const int wn0  = (warp >> 2) * 64;

    auto ld_tile = [&](int kt, int buf) {
        const int k     = kt >> 10;
        const int ci0   = kt & 1023;
        const int shift = 2 * (3 - k);
#pragma unroll
        for (int i = 0; i < 2; i++) {
            int s = tid + i * 256, m = s >> 2, j = (s & 3) << 2;
            int rs = row0 + m - shift;
            cp16(&As[buf][m][j],
                 &h[(size_t)max(rs, 0) * (2 * HH) + grp * 1024 + ci0 + j],
                 rs >= 0);
        }
#pragma unroll
        for (int i = 0; i < 2; i++) {
            int s = tid + i * 256, kk = s >> 5, col = (s & 31) << 2;
            cp16(&Bs[buf][kk][col], &Wc[(size_t)(kt + kk) * HH + col0 + col], true);
        }
        CP_COMMIT();
    };

    float acc[2][8][4];
#pragma unroll
    for (int mt = 0; mt < 2; mt++)
#pragma unroll
        for (int nt = 0; nt < 8; nt++)
#pragma unroll
            for (int q = 0; q < 4; q++) acc[mt][nt][q] = 0.f;

    ld_tile(0, 0);
    CP_WAIT0();
    __syncthreads();

    const int T = (KK * 1024) / BK;
    for (int t = 0; t < T; t++) {
        const int buf = t & 1;
        if (t + 1 < T) ld_tile((t + 1) * BK, buf ^ 1);

#pragma unroll
        for (int ks = 0; ks < 2; ks++) {
            const int k0 = ks * 8;
            unsigned a[2][4], b[8][2];
#pragma unroll
            for (int mt = 0; mt < 2; mt++) {
                int mr = wm0 + mt * 16;
                a[mt][0] = __float_as_uint(As[buf][mr + gid    ][k0 + tig]);
                a[mt][1] = __float_as_uint(As[buf][mr + gid + 8][k0 + tig]);
                a[mt][2] = __float_as_uint(As[buf][mr + gid    ][k0 + tig + 4]);
                a[mt][3] = __float_as_uint(As[buf][mr + gid + 8][k0 + tig + 4]);
            }
#pragma unroll
            for (int nt = 0; nt < 8; nt++) {
                int nc = wn0 + nt * 8;
                b[nt][0] = __float_as_uint(Bs[buf][k0 + tig    ][nc + gid]);
                b[nt][1] = __float_as_uint(Bs[buf][k0 + tig + 4][nc + gid]);
            }
#pragma unroll
            for (int mt = 0; mt < 2; mt++)
#pragma unroll
                for (int nt = 0; nt < 8; nt++)
                    mma_tf32(acc[mt][nt], a[mt], b[nt]);
        }

        if (t + 1 < T) {
            CP_WAIT0();
            __syncthreads();
        }
    }

#pragma unroll
    for (int mt = 0; mt < 2; mt++) {
        int r = row0 + wm0 + mt * 16 + gid;
#pragma unroll
        for (int nt = 0; nt < 8; nt++) {
            int c = col0 + wn0 + nt * 8 + tig * 2;
            float v0 = acc[mt][nt][0] + bconv[c];
            float v1 = acc[mt][nt][1] + bconv[c + 1];
            float v2 = acc[mt][nt][2] + bconv[c];
            float v3 = acc[mt][nt][3] + bconv[c + 1];
            U[(size_t)r * HH + c]           = tf32r(v0 * sigmoid_f(v0));
            U[(size_t)r * HH + c + 1]       = tf32r(v1 * sigmoid_f(v1));
            U[(size_t)(r + 8) * HH + c]     = tf32r(v2 * sigmoid_f(v2));
            U[(size_t)(r + 8) * HH + c + 1] = tf32r(v3 * sigmoid_f(v3));
        }
    }
}

// ---------------- selective scan + fused z = y * silu(res) ----------------
__global__ __launch_bounds__(256)
void scan_k(const float* __restrict__ delta, const float* __restrict__ u,
            const float* __restrict__ proj, const float* __restrict__ A_log,
            const float* __restrict__ D, const float* __restrict__ h,
            float* __restrict__ z)
{
    const int gtid = blockIdx.x * blockDim.x + threadIdx.x;
    const int warp = gtid >> 5;
    const int lane = threadIdx.x & 31;
    const int sub  = lane >> 4;
    const int n    = lane & 15;
    const int c    = warp * 2 + sub;
    const int hi   = c >> 1;
    const int b    = c & 1;

    const float A  = -expf(A_log[hi * NN + n]);
    const float Dh = D[hi];
    float s = 0.f;

    for (int t = 0; t < LL; t++) {
        const int r = t * BB + b;
        float dt = __ldg(&delta[(size_t)r * HH + hi]);
        dt = fminf(fmaxf(dt, 0.001f), 0.1f);
        const float uu = __ldg(&u[(size_t)r * HH + hi]);
        const float Bn = __ldg(&proj[(size_t)r * PROJC + n]);
        const float Cn = __ldg(&proj[(size_t)r * PROJC + NN + n]);

        s = __expf(dt * A) * s + (dt * uu) * Bn;

        float p = Cn * s;
        p += __shfl_xor_sync(0xffffffffu, p, 1);
        p += __shfl_xor_sync(0xffffffffu, p, 2);
        p += __shfl_xor_sync(0xffffffffu, p, 4);
        p += __shfl_xor_sync(0xffffffffu, p, 8);

        if (n == 0) {
            const float yv  = p + uu * Dh;
            const float res = __ldg(&h[(size_t)r * (2 * HH) + HH + hi]);
            z[(size_t)r * HH + hi] = tf32r(yv * (res * sigmoid_f(res)));
        }
    }
}

// ---------------- launch ---------------------------------------------------
extern "C" void kernel_launch(void* const* d_in, const int* in_sizes, int n_in,
                              void* d_out, int out_size)
{
    const float* x      = (const float*)d_in[0];
    const float* W_in   = (const float*)d_in[1];
    const float* W_conv = (const float*)d_in[2];
    const float* b_conv = (const float*)d_in[3];
    const float* A_log  = (const float*)d_in[4];
    const float* D      = (const float*)d_in[5];
    const float* W_ssm  = (const float*)d_in[6];
    const float* W_dt   = (const float*)d_in[7];
    const float* b_dt   = (const float*)d_in[8];
    const float* W_out  = (const float*)d_in[9];
    float* out = (float*)d_out;

    void* p;
    cudaGetSymbolAddress(&p, g_h);      float* hbuf   = (float*)p;
    cudaGetSymbolAddress(&p, g_u);      float* ubuf   = (float*)p;
    cudaGetSymbolAddress(&p, g_proj);   float* pbuf   = (float*)p;
    cudaGetSymbolAddress(&p, g_delta);  float* dbuf   = (float*)p;
    cudaGetSymbolAddress(&p, g_z);      float* zbuf   = (float*)p;
    cudaGetSymbolAddress(&p, g_rx);     float* rx     = (float*)p;
    cudaGetSymbolAddress(&p, g_rWin);   float* rWin   = (float*)p;
    cudaGetSymbolAddress(&p, g_rWc);    float* rWc    = (float*)p;
    cudaGetSymbolAddress(&p, g_rWssm);  float* rWssm  = (float*)p;
    cudaGetSymbolAddress(&p, g_rWdt);   float* rWdt   = (float*)p;
    cudaGetSymbolAddress(&p, g_rWout);  float* rWout  = (float*)p;

    dim3 blk(256);
    auto rq = [&](const float* src, float* dst, size_t n) {
        int n4 = (int)(n / 4);
        round_k<<<(n4 + 255) / 256, blk>>>(src, dst, n4);
    };

    // 0) TF32 pre-round inputs/weights
    rq(x,      rx,    (size_t)MROWS * FF);
    rq(W_in,   rWin,  (size_t)FF * 2 * HH);
    rq(W_conv, rWc,   (size_t)KK * 1024 * HH);
    rq(W_ssm,  rWssm, (size_t)HH * PROJC);
    rq(W_dt,   rWdt,  (size_t)RR * HH);
    rq(W_out,  rWout, (size_t)HH * FF);

    // 1) h = x @ W_in (xs half rounded, res half raw)
    gemm_k<0, 2><<<dim3(2 * HH / BN, MROWS / BM), blk>>>(
        rx, FF, rWin, 2 * HH, hbuf, 2 * HH, 2 * HH, FF, nullptr);

    // 2) u = silu(conv(xs) + b_conv), rounded
    conv_silu_k<<<dim3(HH / BN, MROWS / BM), blk>>>(hbuf, rWc, b_conv, ubuf);

    // 3) proj = u @ W_ssm, rounded
    gemm_k<0, 1><<<dim3(1, MROWS / BM), blk>>>(
        ubuf, HH, rWssm, PROJC, pbuf, PROJC, PROJC, HH, nullptr);

    // 4) delta = softplus(proj[:,32:96] @ W_dt + b_dt), raw
    gemm_k<1, 0><<<dim3(HH / BN, MROWS / BM), blk>>>(
        pbuf + 2 * NN, PROJC, rWdt, HH, dbuf, HH, HH, RR, b_dt);

    // 5) selective scan + z = y * silu(res), rounded
    scan_k<<<BB * HH * NN / 256, blk>>>(dbuf, ubuf, pbuf, A_log, D, hbuf, zbuf);

    // 6) out = z @ W_out, raw
    gemm_k<0, 0><<<dim3(FF / BN, MROWS / BM), blk>>>(
        zbuf, HH, rWout, FF, out, FF, FF, HH, nullptr);
}